// round 8
// baseline (speedup 1.0000x reference)
#include <cuda_runtime.h>
#include <cstdint>

#define NN 50000
#define NE 800000
#define KIN 166
#define HID 128
#define BN_EPS 1e-5f

// ---------------------------------------------------------------------------
// Scratch (device globals — no allocation allowed). 16B-aligned for vector ld/st.
// ---------------------------------------------------------------------------
__device__ __align__(16) float g_y  [NN * HID];   // lin_l-transformed features
__device__ __align__(16) float g_r  [NN * HID];   // lin_r output
__device__ __align__(16) float g_p  [NN * HID];   // residual projection (layer 0)
__device__ __align__(16) float g_h0 [NN * HID];
__device__ __align__(16) float g_h1 [NN * HID];
__device__ float g_inv[NN];         // 1 / max(in_degree, 1)
__device__ int   g_deg[NN];
__device__ int   g_rowstart[NN + 1];
__device__ int   g_cursor[NN];
__device__ int   g_csrc[NE];        // CSR-by-dst: source node per edge slot
__device__ __align__(16) float g_z2[NN * 2];
__device__ int   g_is64;            // runtime-detected edge_index dtype

// ---------------------------------------------------------------------------
// Packed fp32x2 FMA (B300: 2x fp32 throughput, exact fp32 per half)
// ---------------------------------------------------------------------------
__device__ __forceinline__ void ffma2(unsigned long long& d,
                                      unsigned long long a,
                                      unsigned long long b) {
    asm volatile("fma.rn.f32x2 %0, %1, %2, %0;" : "+l"(d) : "l"(a), "l"(b));
}
__device__ __forceinline__ void unpack2(unsigned long long v, float& lo, float& hi) {
    asm("mov.b64 {%0, %1}, %2;" : "=f"(lo), "=f"(hi) : "l"(v));
}

// ---------------------------------------------------------------------------
// Edge dtype detection: interpret first 512 entries as int64. If edge_index
// is really int32, a "value" is lo + hi*2^32 (hi = the NEXT id) which is
// >= NN unless hi == 0 — over 512 samples that is detected w.p. ~1.
// ---------------------------------------------------------------------------
__global__ void detect_k(const void* ei_raw) {
    if (threadIdx.x == 0) {
        const long long* p = (const long long*)ei_raw;
        int ok64 = 1;
        for (int i = 0; i < 512; i++) {
            long long v = p[i];
            if (v < 0 || v >= NN) { ok64 = 0; break; }
        }
        g_is64 = ok64;
    }
}

__device__ __forceinline__ int edge_src(const void* ei, int e) {
    return g_is64 ? (int)((const long long*)ei)[e] : ((const int*)ei)[e];
}
__device__ __forceinline__ int edge_dst(const void* ei, int e) {
    return g_is64 ? (int)((const long long*)ei)[NE + e] : ((const int*)ei)[NE + e];
}

// ---------------------------------------------------------------------------
// Prologue kernels: degree, prefix sum (CSR), cursor, inv-degree
// ---------------------------------------------------------------------------
__global__ void zero_i(int* __restrict__ p, int n) {
    int i = blockIdx.x * blockDim.x + threadIdx.x;
    if (i < n) p[i] = 0;
}

__global__ void degree_k(const void* __restrict__ ei) {
    int e = blockIdx.x * blockDim.x + threadIdx.x;
    if (e < NE) {
        int d = edge_dst(ei, e);
        atomicAdd(&g_deg[d], 1);
    }
}

// Single-block exclusive prefix sum over g_deg (warp-scan based).
__global__ __launch_bounds__(1024) void scan_k() {
    __shared__ int wsum[32];
    __shared__ int s_carry;
    const int tid  = threadIdx.x;
    const int lane = tid & 31;
    const int wid  = tid >> 5;
    if (tid == 0) s_carry = 0;
    __syncthreads();

    for (int base = 0; base < NN; base += 1024) {
        int i = base + tid;
        int v = (i < NN) ? g_deg[i] : 0;
        int incl = v;
#pragma unroll
        for (int o = 1; o < 32; o <<= 1) {
            int t = __shfl_up_sync(0xffffffffu, incl, o);
            if (lane >= o) incl += t;
        }
        if (lane == 31) wsum[wid] = incl;
        __syncthreads();
        if (wid == 0) {
            int wv = wsum[lane];
            int wi = wv;
#pragma unroll
            for (int o = 1; o < 32; o <<= 1) {
                int t = __shfl_up_sync(0xffffffffu, wi, o);
                if (lane >= o) wi += t;
            }
            wsum[lane] = wi - wv;   // exclusive warp offsets
        }
        __syncthreads();
        int excl = incl - v + wsum[wid] + s_carry;
        if (i < NN) {
            g_rowstart[i] = excl;
            g_cursor[i]   = excl;
            g_inv[i]      = 1.f / (float)(v > 1 ? v : 1);
        }
        __syncthreads();
        if (tid == 1023) s_carry = excl + v;
        __syncthreads();
    }
    if (tid == 0) g_rowstart[NN] = s_carry;
}

__global__ void fill_k(const void* __restrict__ ei) {
    int e = blockIdx.x * blockDim.x + threadIdx.x;
    if (e >= NE) return;
    int s = edge_src(ei, e);
    int d = edge_dst(ei, e);
    int pos = atomicAdd(&g_cursor[d], 1);
    g_csrc[pos] = s;
}

// ---------------------------------------------------------------------------
// Batched SGEMM with FFMA2 + double-buffered smem. Slice s = blockIdx.y:
//   C[s][M x 128] = A[M x K] @ W[s]^T, W[s] is [128 x K] row-major.
// 128x128 tile, BK=8, 256 threads, 8x8 micro-tile as 4 packed row-pairs.
// One __syncthreads per k-step; next tile's LDGs issued before compute.
// ---------------------------------------------------------------------------
__global__ __launch_bounds__(256) void sgemm_n128_b(
    const float* __restrict__ A,
    const float* __restrict__ W0, const float* __restrict__ W1,
    const float* __restrict__ W2,
    float* __restrict__ C0, float* __restrict__ C1, float* __restrict__ C2,
    int M, int K)
{
    const float* W = (blockIdx.y == 0) ? W0 : (blockIdx.y == 1) ? W1 : W2;
    float*       C = (blockIdx.y == 0) ? C0 : (blockIdx.y == 1) ? C1 : C2;

    __shared__ __align__(16) float As [2][8][128];   // [buf][k][row]
    __shared__ __align__(16) float Wsd[2][8][256];   // [buf][k][2*col] dup {b,b}

    const int t    = threadIdx.x;
    const int m0   = blockIdx.x * 128;
    const int ty   = t >> 4;
    const int tx   = t & 15;
    const int lrow = t >> 1;        // 0..127
    const int lk   = (t & 1) * 4;   // 0 or 4
    const int am   = m0 + lrow;

    unsigned long long acc[4][8];
#pragma unroll
    for (int i = 0; i < 4; i++)
#pragma unroll
        for (int j = 0; j < 8; j++) acc[i][j] = 0ull;

    float a_reg[4], w_reg[4];

    // prologue: load tile k0=0 into buffer 0
#pragma unroll
    for (int i = 0; i < 4; i++) {
        int k = lk + i;
        a_reg[i] = (am < M && k < K) ? A[(size_t)am * K + k] : 0.f;
        w_reg[i] = (k < K) ? W[(size_t)lrow * K + k] : 0.f;
    }
#pragma unroll
    for (int i = 0; i < 4; i++) {
        As[0][lk + i][lrow] = a_reg[i];
        *(float2*)&Wsd[0][lk + i][2 * lrow] = make_float2(w_reg[i], w_reg[i]);
    }
    __syncthreads();

    const int nsteps = (K + 7) / 8;
    for (int it = 0; it < nsteps; it++) {
        const int cur = it & 1;
        const bool has_next = (it + 1 < nsteps);

        // issue next tile's global loads first (latency hidden by compute)
        if (has_next) {
            int k0n = (it + 1) * 8;
#pragma unroll
            for (int i = 0; i < 4; i++) {
                int k = k0n + lk + i;
                a_reg[i] = (am < M && k < K) ? A[(size_t)am * K + k] : 0.f;
                w_reg[i] = (k < K) ? W[(size_t)lrow * K + k] : 0.f;
            }
        }

        // compute on current buffer
        ulonglong2 A0 = *(const ulonglong2*)&As[cur][0][ty * 8];
        ulonglong2 A1 = *(const ulonglong2*)&As[cur][0][ty * 8 + 4];
        ulonglong2 B0 = *(const ulonglong2*)&Wsd[cur][0][tx * 16];
        ulonglong2 B1 = *(const ulonglong2*)&Wsd[cur][0][tx * 16 + 4];
        ulonglong2 B2 = *(const ulonglong2*)&Wsd[cur][0][tx * 16 + 8];
        ulonglong2 B3 = *(const ulonglong2*)&Wsd[cur][0][tx * 16 + 12];
#pragma unroll
        for (int kk = 0; kk < 8; kk++) {
            unsigned long long ap[4] = {A0.x, A0.y, A1.x, A1.y};
            unsigned long long bb[8] = {B0.x, B0.y, B1.x, B1.y,
                                        B2.x, B2.y, B3.x, B3.y};
            if (kk < 7) {
                A0 = *(const ulonglong2*)&As[cur][kk + 1][ty * 8];
                A1 = *(const ulonglong2*)&As[cur][kk + 1][ty * 8 + 4];
                B0 = *(const ulonglong2*)&Wsd[cur][kk + 1][tx * 16];
                B1 = *(const ulonglong2*)&Wsd[cur][kk + 1][tx * 16 + 4];
                B2 = *(const ulonglong2*)&Wsd[cur][kk + 1][tx * 16 + 8];
                B3 = *(const ulonglong2*)&Wsd[cur][kk + 1][tx * 16 + 12];
            }
#pragma unroll
            for (int i = 0; i < 4; i++)
#pragma unroll
                for (int j = 0; j < 8; j++)
                    ffma2(acc[i][j], ap[i], bb[j]);
        }

        // stage next tile into the alternate buffer
        if (has_next) {
            const int nxt = cur ^ 1;
#pragma unroll
            for (int i = 0; i < 4; i++) {
                As[nxt][lk + i][lrow] = a_reg[i];
                *(float2*)&Wsd[nxt][lk + i][2 * lrow] = make_float2(w_reg[i], w_reg[i]);
            }
            __syncthreads();
        }
    }

#pragma unroll
    for (int i = 0; i < 4; i++) {
        float lo[8], hi[8];
#pragma unroll
        for (int j = 0; j < 8; j++) unpack2(acc[i][j], lo[j], hi[j]);
        int r0 = m0 + ty * 8 + 2 * i;
        if (r0 < M) {
            float4* cp = (float4*)&C[(size_t)r0 * 128 + tx * 8];
            cp[0] = make_float4(lo[0], lo[1], lo[2], lo[3]);
            cp[1] = make_float4(lo[4], lo[5], lo[6], lo[7]);
        }
        if (r0 + 1 < M) {
            float4* cp = (float4*)&C[(size_t)(r0 + 1) * 128 + tx * 8];
            cp[0] = make_float4(hi[0], hi[1], hi[2], hi[3]);
            cp[1] = make_float4(hi[4], hi[5], hi[6], hi[7]);
        }
    }
}

// ---------------------------------------------------------------------------
// Fused CSR aggregation + epilogue: one warp per destination node.
// h[n] = relu(bn(mean_{s in N(n)} y[s] + bl + r[n])) + res[n]
// Lane holds channels [lane*4, lane*4+4). Gather loop unrolled x4 for MLP.
// ---------------------------------------------------------------------------
__global__ __launch_bounds__(256) void agg_epi_k(
    const float* __restrict__ y, const float* __restrict__ r,
    const float* __restrict__ res, const float* __restrict__ bl,
    const float* __restrict__ gam, const float* __restrict__ bet,
    const float* __restrict__ mu,  const float* __restrict__ var,
    float* __restrict__ h)
{
    long long gid = (long long)blockIdx.x * blockDim.x + threadIdx.x;
    int node = (int)(gid >> 5);
    if (node >= NN) return;
    int lane = threadIdx.x & 31;

    int beg = g_rowstart[node];
    int end = g_rowstart[node + 1];

    float4 acc = make_float4(0.f, 0.f, 0.f, 0.f);
    int j = beg;
    for (; j + 3 < end; j += 4) {
        int s0 = g_csrc[j];
        int s1 = g_csrc[j + 1];
        int s2 = g_csrc[j + 2];
        int s3 = g_csrc[j + 3];
        float4 v0 = ((const float4*)(y + (size_t)s0 * 128))[lane];
        float4 v1 = ((const float4*)(y + (size_t)s1 * 128))[lane];
        float4 v2 = ((const float4*)(y + (size_t)s2 * 128))[lane];
        float4 v3 = ((const float4*)(y + (size_t)s3 * 128))[lane];
        acc.x += (v0.x + v1.x) + (v2.x + v3.x);
        acc.y += (v0.y + v1.y) + (v2.y + v3.y);
        acc.z += (v0.z + v1.z) + (v2.z + v3.z);
        acc.w += (v0.w + v1.w) + (v2.w + v3.w);
    }
    for (; j < end; j++) {
        int s0 = g_csrc[j];
        float4 v0 = ((const float4*)(y + (size_t)s0 * 128))[lane];
        acc.x += v0.x; acc.y += v0.y; acc.z += v0.z; acc.w += v0.w;
    }

    float iv = g_inv[node];
    int c = lane * 4;
    size_t idx = (size_t)node * 128 + c;
    float4 blv  = *(const float4*)(bl  + c);
    float4 gamv = *(const float4*)(gam + c);
    float4 betv = *(const float4*)(bet + c);
    float4 muv  = *(const float4*)(mu  + c);
    float4 varv = *(const float4*)(var + c);
    float4 rv   = *(const float4*)(r   + idx);
    float4 resv = *(const float4*)(res + idx);

    float4 o;
    {
        float s0 = gamv.x * rsqrtf(varv.x + BN_EPS);
        float s1 = gamv.y * rsqrtf(varv.y + BN_EPS);
        float s2 = gamv.z * rsqrtf(varv.z + BN_EPS);
        float s3 = gamv.w * rsqrtf(varv.w + BN_EPS);
        float p0 = acc.x * iv + blv.x + rv.x;
        float p1 = acc.y * iv + blv.y + rv.y;
        float p2 = acc.z * iv + blv.z + rv.z;
        float p3 = acc.w * iv + blv.w + rv.w;
        o.x = fmaxf((p0 - muv.x) * s0 + betv.x, 0.f) + resv.x;
        o.y = fmaxf((p1 - muv.y) * s1 + betv.y, 0.f) + resv.y;
        o.z = fmaxf((p2 - muv.z) * s2 + betv.z, 0.f) + resv.z;
        o.w = fmaxf((p3 - muv.w) * s3 + betv.w, 0.f) + resv.w;
    }
    *(float4*)(h + idx) = o;
}

// ---------------------------------------------------------------------------
// Layer 2: z2[i] = h1[i] @ Wl2^T  (128 -> 2), one warp per node
// ---------------------------------------------------------------------------
__global__ void z2_k(const float* __restrict__ h, const float* __restrict__ Wl2) {
    long long gid = (long long)blockIdx.x * blockDim.x + threadIdx.x;
    int node = (int)(gid >> 5);
    if (node >= NN) return;
    int lane = threadIdx.x & 31;
    float4 hv = ((const float4*)(h + (size_t)node * 128))[lane];
    float4 w0 = ((const float4*)Wl2)[lane];
    float4 w1 = ((const float4*)(Wl2 + 128))[lane];
    float d0 = hv.x * w0.x + hv.y * w0.y + hv.z * w0.z + hv.w * w0.w;
    float d1 = hv.x * w1.x + hv.y * w1.y + hv.z * w1.z + hv.w * w1.w;
#pragma unroll
    for (int o = 16; o; o >>= 1) {
        d0 += __shfl_xor_sync(0xffffffffu, d0, o);
        d1 += __shfl_xor_sync(0xffffffffu, d1, o);
    }
    if (lane == 0) {
        g_z2[node * 2]     = d0;
        g_z2[node * 2 + 1] = d1;
    }
}

// Output: out[n] = mean_{s in N(n)} z2[s] + bl2 + h1[n] @ Wr2^T ; warp per node.
__global__ void out2_k(const float* __restrict__ h, const float* __restrict__ Wr2,
                       const float* __restrict__ bl2, float* __restrict__ out) {
    long long gid = (long long)blockIdx.x * blockDim.x + threadIdx.x;
    int node = (int)(gid >> 5);
    if (node >= NN) return;
    int lane = threadIdx.x & 31;

    float4 hv = ((const float4*)(h + (size_t)node * 128))[lane];
    float4 w0 = ((const float4*)Wr2)[lane];
    float4 w1 = ((const float4*)(Wr2 + 128))[lane];
    float d0 = hv.x * w0.x + hv.y * w0.y + hv.z * w0.z + hv.w * w0.w;
    float d1 = hv.x * w1.x + hv.y * w1.y + hv.z * w1.z + hv.w * w1.w;

    int beg = g_rowstart[node];
    int end = g_rowstart[node + 1];
    float a0 = 0.f, a1 = 0.f;
    for (int j = beg + lane; j < end; j += 32) {
        int s = g_csrc[j];
        float2 v = ((const float2*)g_z2)[s];
        a0 += v.x; a1 += v.y;
    }
#pragma unroll
    for (int o = 16; o; o >>= 1) {
        d0 += __shfl_xor_sync(0xffffffffu, d0, o);
        d1 += __shfl_xor_sync(0xffffffffu, d1, o);
        a0 += __shfl_xor_sync(0xffffffffu, a0, o);
        a1 += __shfl_xor_sync(0xffffffffu, a1, o);
    }
    if (lane == 0) {
        float iv = g_inv[node];
        out[node * 2]     = a0 * iv + bl2[0] + d0;
        out[node * 2 + 1] = a1 * iv + bl2[1] + d1;
    }
}

// ---------------------------------------------------------------------------
// Launch
// ---------------------------------------------------------------------------
extern "C" void kernel_launch(void* const* d_in, const int* in_sizes, int n_in,
                              void* d_out, int out_size)
{
    const float* x     = (const float*)d_in[0];
    const void*  ei    = d_in[1];                 // dtype runtime-detected
    const float* Wl0   = (const float*)d_in[2];
    const float* bl0   = (const float*)d_in[3];
    const float* Wr0   = (const float*)d_in[4];
    const float* Wl1   = (const float*)d_in[5];
    const float* bl1   = (const float*)d_in[6];
    const float* Wr1   = (const float*)d_in[7];
    const float* Wl2   = (const float*)d_in[8];
    const float* bl2   = (const float*)d_in[9];
    const float* Wr2   = (const float*)d_in[10];
    const float* Wres0 = (const float*)d_in[11];
    const float* bn0g  = (const float*)d_in[12];
    const float* bn0b  = (const float*)d_in[13];
    const float* bn0m  = (const float*)d_in[14];
    const float* bn0v  = (const float*)d_in[15];
    const float* bn1g  = (const float*)d_in[16];
    const float* bn1b  = (const float*)d_in[17];
    const float* bn1m  = (const float*)d_in[18];
    const float* bn1v  = (const float*)d_in[19];
    float* out = (float*)d_out;

    float *y, *r, *p, *h0, *h1;
    int* deg;
    cudaGetSymbolAddress((void**)&y,   g_y);
    cudaGetSymbolAddress((void**)&r,   g_r);
    cudaGetSymbolAddress((void**)&p,   g_p);
    cudaGetSymbolAddress((void**)&h0,  g_h0);
    cudaGetSymbolAddress((void**)&h1,  g_h1);
    cudaGetSymbolAddress((void**)&deg, g_deg);

    const int T = 256;
    const int gemm_bx = (NN + 127) / 128;                     // 391
    const int node_warp_blocks = (NN * 32 + T - 1) / T;       // 6250

    // ----- CSR build (graph is an input; rebuilt each launch) -----
    detect_k<<<1, 32>>>(ei);
    zero_i<<<(NN + T - 1) / T, T>>>(deg, NN);
    degree_k<<<(NE + T - 1) / T, T>>>(ei);
    scan_k<<<1, 1024>>>();
    fill_k<<<(NE + T - 1) / T, T>>>(ei);

    // ----- layer 0: 3 GEMMs in one launch, then fused agg+BN+ReLU+res -----
    sgemm_n128_b<<<dim3(gemm_bx, 3), T>>>(x, Wl0, Wr0, Wres0, y, r, p, NN, KIN);
    agg_epi_k<<<node_warp_blocks, T>>>(y, r, p, bl0, bn0g, bn0b, bn0m, bn0v, h0);

    // ----- layer 1 -----
    sgemm_n128_b<<<dim3(gemm_bx, 2), T>>>(h0, Wl1, Wr1, Wr1, y, r, r, NN, HID);
    agg_epi_k<<<node_warp_blocks, T>>>(y, r, h0, bl1, bn1g, bn1b, bn1m, bn1v, h1);

    // ----- layer 2: transform to 2 dims first, then gather-side mean -----
    z2_k<<<node_warp_blocks, T>>>(h1, Wl2);
    out2_k<<<node_warp_blocks, T>>>(h1, Wr2, bl2, out);
}

// round 11
// speedup vs baseline: 2.0338x; 2.0338x over previous
#include <cuda_runtime.h>
#include <cstdint>

#define NN 50000
#define NE 800000
#define KIN 166
#define HID 128
#define BN_EPS 1e-5f
#define SCAN_B 256
#define NBLK ((NN + SCAN_B - 1) / SCAN_B)   // 196

// ---------------------------------------------------------------------------
// Scratch (device globals — no allocation allowed). 16B-aligned for vector ld/st.
// ---------------------------------------------------------------------------
__device__ __align__(16) float g_y  [NN * HID];   // lin_l-transformed features
__device__ __align__(16) float g_r  [NN * HID];   // lin_r output
__device__ __align__(16) float g_p  [NN * HID];   // residual projection (layer 0)
__device__ __align__(16) float g_h0 [NN * HID];
__device__ __align__(16) float g_h1 [NN * HID];
__device__ float g_inv[NN];         // 1 / max(in_degree, 1)
__device__ int   g_deg[NN];
__device__ int   g_rowstart[NN + 1];
__device__ int   g_cursor[NN];
__device__ int   g_csrc[NE];        // CSR-by-dst: source node per edge slot
__device__ __align__(16) float g_z2[NN * 2];
__device__ int   g_is64;            // runtime-detected edge_index dtype
__device__ int   g_bsum[NBLK];
__device__ int   g_boff[NBLK];

// ---------------------------------------------------------------------------
// Packed fp32x2 FMA (B300: 2x fp32 throughput, exact fp32 per half)
// ---------------------------------------------------------------------------
__device__ __forceinline__ void ffma2(unsigned long long& d,
                                      unsigned long long a,
                                      unsigned long long b) {
    asm volatile("fma.rn.f32x2 %0, %1, %2, %0;" : "+l"(d) : "l"(a), "l"(b));
}
__device__ __forceinline__ void unpack2(unsigned long long v, float& lo, float& hi) {
    asm("mov.b64 {%0, %1}, %2;" : "=f"(lo), "=f"(hi) : "l"(v));
}

// ---------------------------------------------------------------------------
// Edge dtype detection (32 lanes, ballot). int32 data read as int64 gives
// values >= NN except when the paired hi word is 0 — 512 samples suffice.
// ---------------------------------------------------------------------------
__global__ void detect_k(const void* ei_raw) {
    const long long* p = (const long long*)ei_raw;
    int lane = threadIdx.x;
    int ok = 1;
#pragma unroll
    for (int i = 0; i < 16; i++) {
        long long v = p[lane * 16 + i];
        if (v < 0 || v >= NN) ok = 0;
    }
    unsigned m = __ballot_sync(0xffffffffu, ok);
    if (lane == 0) g_is64 = (m == 0xffffffffu) ? 1 : 0;
}

__device__ __forceinline__ int edge_src(const void* ei, int e) {
    return g_is64 ? (int)((const long long*)ei)[e] : ((const int*)ei)[e];
}
__device__ __forceinline__ int edge_dst(const void* ei, int e) {
    return g_is64 ? (int)((const long long*)ei)[NE + e] : ((const int*)ei)[NE + e];
}

// ---------------------------------------------------------------------------
// CSR prologue
// ---------------------------------------------------------------------------
__global__ void zero_i(int* __restrict__ p, int n) {
    int i = blockIdx.x * blockDim.x + threadIdx.x;
    if (i < n) p[i] = 0;
}

__global__ void degree_k(const void* __restrict__ ei) {
    int e = blockIdx.x * blockDim.x + threadIdx.x;
    if (e < NE) atomicAdd(&g_deg[edge_dst(ei, e)], 1);
}

// per-block sums of g_deg
__global__ __launch_bounds__(SCAN_B) void bsum_k() {
    __shared__ int ws[SCAN_B / 32];
    int i = blockIdx.x * SCAN_B + threadIdx.x;
    int lane = threadIdx.x & 31, w = threadIdx.x >> 5;
    int v = (i < NN) ? g_deg[i] : 0;
    int s = v;
#pragma unroll
    for (int o = 16; o; o >>= 1) s += __shfl_xor_sync(0xffffffffu, s, o);
    if (lane == 0) ws[w] = s;
    __syncthreads();
    if (threadIdx.x == 0) {
        int tot = 0;
#pragma unroll
        for (int k = 0; k < SCAN_B / 32; k++) tot += ws[k];
        g_bsum[blockIdx.x] = tot;
    }
}

// single-block exclusive scan of the NBLK block sums
__global__ __launch_bounds__(256) void bscan_k() {
    __shared__ int ws[8];
    int t = threadIdx.x, lane = t & 31, w = t >> 5;
    int v = (t < NBLK) ? g_bsum[t] : 0;
    int incl = v;
#pragma unroll
    for (int o = 1; o < 32; o <<= 1) {
        int x = __shfl_up_sync(0xffffffffu, incl, o);
        if (lane >= o) incl += x;
    }
    if (lane == 31) ws[w] = incl;
    __syncthreads();
    if (w == 0 && lane < 8) {
        int wv = ws[lane];
        int wi = wv;
#pragma unroll
        for (int o = 1; o < 8; o <<= 1) {
            int x = __shfl_up_sync(0xffu, wi, o);
            if (lane >= o) wi += x;
        }
        ws[lane] = wi - wv;
    }
    __syncthreads();
    if (t < NBLK) g_boff[t] = incl - v + ws[w];
    if (t == 0) g_rowstart[NN] = NE;
}

// per-block local exclusive scan + block offset -> rowstart/cursor/inv
__global__ __launch_bounds__(SCAN_B) void rowstart_k() {
    __shared__ int ws[SCAN_B / 32];
    int i = blockIdx.x * SCAN_B + threadIdx.x;
    int lane = threadIdx.x & 31, w = threadIdx.x >> 5;
    int v = (i < NN) ? g_deg[i] : 0;
    int incl = v;
#pragma unroll
    for (int o = 1; o < 32; o <<= 1) {
        int x = __shfl_up_sync(0xffffffffu, incl, o);
        if (lane >= o) incl += x;
    }
    if (lane == 31) ws[w] = incl;
    __syncthreads();
    if (w == 0 && lane < SCAN_B / 32) {
        int wv = ws[lane];
        int wi = wv;
#pragma unroll
        for (int o = 1; o < SCAN_B / 32; o <<= 1) {
            int x = __shfl_up_sync(0xffu, wi, o);
            if (lane >= o) wi += x;
        }
        ws[lane] = wi - wv;
    }
    __syncthreads();
    if (i < NN) {
        int excl = incl - v + ws[w] + g_boff[blockIdx.x];
        g_rowstart[i] = excl;
        g_cursor[i]   = excl;
        g_inv[i]      = 1.f / (float)(v > 1 ? v : 1);
    }
}

__global__ void fill_k(const void* __restrict__ ei) {
    int e = blockIdx.x * blockDim.x + threadIdx.x;
    if (e >= NE) return;
    int s = edge_src(ei, e);
    int d = edge_dst(ei, e);
    int pos = atomicAdd(&g_cursor[d], 1);
    g_csrc[pos] = s;
}

// ---------------------------------------------------------------------------
// Batched SGEMM, FFMA2, double-buffered, CONFLICT-FREE B layout.
//   C[s][M x 128] = A[M x K] @ W[s]^T  (slice s = blockIdx.y)
// Thread (ty=t>>4, tx=t&15): rows ty*8..+7 (4 packed pairs),
// cols 2tx + 32j + {0,1} for j=0..3 (strided column mapping).
// B stored duplicated {b,b}: one LDS.128 at 16B*tx + 256B*j yields two packed
// multiplier pairs; lanes of a phase hit banks 4tx..4tx+3 -> conflict-free.
// ---------------------------------------------------------------------------
__global__ __launch_bounds__(256) void sgemm_n128_b(
    const float* __restrict__ A,
    const float* __restrict__ W0, const float* __restrict__ W1,
    const float* __restrict__ W2,
    float* __restrict__ C0, float* __restrict__ C1, float* __restrict__ C2,
    int M, int K)
{
    const float* W = (blockIdx.y == 0) ? W0 : (blockIdx.y == 1) ? W1 : W2;
    float*       C = (blockIdx.y == 0) ? C0 : (blockIdx.y == 1) ? C1 : C2;

    __shared__ __align__(16) float As [2][8][128];   // [buf][k][row]
    __shared__ __align__(16) float Wsd[2][8][256];   // [buf][k][2*col] dup {b,b}

    const int t    = threadIdx.x;
    const int m0   = blockIdx.x * 128;
    const int ty   = t >> 4;        // 0..15
    const int tx   = t & 15;        // 0..15
    const int lrow = t >> 1;        // 0..127 (A row / W col for loading)
    const int lk   = (t & 1) * 4;   // 0 or 4
    const int am   = m0 + lrow;

    unsigned long long acc[4][8];   // [row-pair][colslot]: colslot 2j+{0,1} -> col 2tx+32j+{0,1}
#pragma unroll
    for (int i = 0; i < 4; i++)
#pragma unroll
        for (int j = 0; j < 8; j++) acc[i][j] = 0ull;

    float a_reg[4], w_reg[4];

    // prologue: tile 0 into buffer 0
#pragma unroll
    for (int i = 0; i < 4; i++) {
        int k = lk + i;
        a_reg[i] = (am < M && k < K) ? A[(size_t)am * K + k] : 0.f;
        w_reg[i] = (k < K) ? W[(size_t)lrow * K + k] : 0.f;
    }
#pragma unroll
    for (int i = 0; i < 4; i++) {
        As[0][lk + i][lrow] = a_reg[i];
        *(float2*)&Wsd[0][lk + i][2 * lrow] = make_float2(w_reg[i], w_reg[i]);
    }
    __syncthreads();

    const int nsteps = (K + 7) / 8;
    for (int it = 0; it < nsteps; it++) {
        const int cur = it & 1;
        const bool has_next = (it + 1 < nsteps);

        if (has_next) {
            int k0n = (it + 1) * 8;
#pragma unroll
            for (int i = 0; i < 4; i++) {
                int k = k0n + lk + i;
                a_reg[i] = (am < M && k < K) ? A[(size_t)am * K + k] : 0.f;
                w_reg[i] = (k < K) ? W[(size_t)lrow * K + k] : 0.f;
            }
        }

#pragma unroll
        for (int kk = 0; kk < 8; kk++) {
            ulonglong2 A0 = *(const ulonglong2*)&As[cur][kk][ty * 8];      // row pairs (0,1),(2,3)
            ulonglong2 A1 = *(const ulonglong2*)&As[cur][kk][ty * 8 + 4];  // (4,5),(6,7)
            ulonglong2 Bp0 = *(const ulonglong2*)&Wsd[cur][kk][4 * tx];        // cols 2tx, 2tx+1
            ulonglong2 Bp1 = *(const ulonglong2*)&Wsd[cur][kk][4 * tx + 64];   // +32
            ulonglong2 Bp2 = *(const ulonglong2*)&Wsd[cur][kk][4 * tx + 128];  // +64
            ulonglong2 Bp3 = *(const ulonglong2*)&Wsd[cur][kk][4 * tx + 192];  // +96
            unsigned long long ap[4] = {A0.x, A0.y, A1.x, A1.y};
            unsigned long long bb[8] = {Bp0.x, Bp0.y, Bp1.x, Bp1.y,
                                        Bp2.x, Bp2.y, Bp3.x, Bp3.y};
#pragma unroll
            for (int i = 0; i < 4; i++)
#pragma unroll
                for (int j = 0; j < 8; j++)
                    ffma2(acc[i][j], ap[i], bb[j]);
        }

        if (has_next) {
            const int nxt = cur ^ 1;
#pragma unroll
            for (int i = 0; i < 4; i++) {
                As[nxt][lk + i][lrow] = a_reg[i];
                *(float2*)&Wsd[nxt][lk + i][2 * lrow] = make_float2(w_reg[i], w_reg[i]);
            }
            __syncthreads();
        }
    }

    // epilogue: strided columns, float2 stores (adjacent col pair per store)
#pragma unroll
    for (int i = 0; i < 4; i++) {
        int r0 = m0 + ty * 8 + 2 * i;
#pragma unroll
        for (int j = 0; j < 4; j++) {
            float l0, h0, l1, h1;
            unpack2(acc[i][2 * j],     l0, h0);
            unpack2(acc[i][2 * j + 1], l1, h1);
            int c = 2 * tx + 32 * j;
            if (r0 < M)     *(float2*)&C[(size_t)r0 * 128 + c]       = make_float2(l0, l1);
            if (r0 + 1 < M) *(float2*)&C[(size_t)(r0 + 1) * 128 + c] = make_float2(h0, h1);
        }
    }
}

// ---------------------------------------------------------------------------
// Fused CSR aggregation + epilogue: one warp per destination node.
// h[n] = relu(bn(mean_{s in N(n)} y[s] + bl + r[n])) + res[n]
// ---------------------------------------------------------------------------
__global__ __launch_bounds__(256) void agg_epi_k(
    const float* __restrict__ y, const float* __restrict__ r,
    const float* __restrict__ res, const float* __restrict__ bl,
    const float* __restrict__ gam, const float* __restrict__ bet,
    const float* __restrict__ mu,  const float* __restrict__ var,
    float* __restrict__ h)
{
    long long gid = (long long)blockIdx.x * blockDim.x + threadIdx.x;
    int node = (int)(gid >> 5);
    if (node >= NN) return;
    int lane = threadIdx.x & 31;

    int beg = g_rowstart[node];
    int end = g_rowstart[node + 1];

    float4 acc = make_float4(0.f, 0.f, 0.f, 0.f);
    int j = beg;
    for (; j + 3 < end; j += 4) {
        int s0 = g_csrc[j];
        int s1 = g_csrc[j + 1];
        int s2 = g_csrc[j + 2];
        int s3 = g_csrc[j + 3];
        float4 v0 = ((const float4*)(y + (size_t)s0 * 128))[lane];
        float4 v1 = ((const float4*)(y + (size_t)s1 * 128))[lane];
        float4 v2 = ((const float4*)(y + (size_t)s2 * 128))[lane];
        float4 v3 = ((const float4*)(y + (size_t)s3 * 128))[lane];
        acc.x += (v0.x + v1.x) + (v2.x + v3.x);
        acc.y += (v0.y + v1.y) + (v2.y + v3.y);
        acc.z += (v0.z + v1.z) + (v2.z + v3.z);
        acc.w += (v0.w + v1.w) + (v2.w + v3.w);
    }
    for (; j < end; j++) {
        int s0 = g_csrc[j];
        float4 v0 = ((const float4*)(y + (size_t)s0 * 128))[lane];
        acc.x += v0.x; acc.y += v0.y; acc.z += v0.z; acc.w += v0.w;
    }

    float iv = g_inv[node];
    int c = lane * 4;
    size_t idx = (size_t)node * 128 + c;
    float4 blv  = *(const float4*)(bl  + c);
    float4 gamv = *(const float4*)(gam + c);
    float4 betv = *(const float4*)(bet + c);
    float4 muv  = *(const float4*)(mu  + c);
    float4 varv = *(const float4*)(var + c);
    float4 rv   = *(const float4*)(r   + idx);
    float4 resv = *(const float4*)(res + idx);

    float4 o;
    {
        float s0 = gamv.x * rsqrtf(varv.x + BN_EPS);
        float s1 = gamv.y * rsqrtf(varv.y + BN_EPS);
        float s2 = gamv.z * rsqrtf(varv.z + BN_EPS);
        float s3 = gamv.w * rsqrtf(varv.w + BN_EPS);
        float p0 = acc.x * iv + blv.x + rv.x;
        float p1 = acc.y * iv + blv.y + rv.y;
        float p2 = acc.z * iv + blv.z + rv.z;
        float p3 = acc.w * iv + blv.w + rv.w;
        o.x = fmaxf((p0 - muv.x) * s0 + betv.x, 0.f) + resv.x;
        o.y = fmaxf((p1 - muv.y) * s1 + betv.y, 0.f) + resv.y;
        o.z = fmaxf((p2 - muv.z) * s2 + betv.z, 0.f) + resv.z;
        o.w = fmaxf((p3 - muv.w) * s3 + betv.w, 0.f) + resv.w;
    }
    *(float4*)(h + idx) = o;
}

// ---------------------------------------------------------------------------
// Layer 2: z2[i] = h1[i] @ Wl2^T  (128 -> 2), one warp per node
// ---------------------------------------------------------------------------
__global__ void z2_k(const float* __restrict__ h, const float* __restrict__ Wl2) {
    long long gid = (long long)blockIdx.x * blockDim.x + threadIdx.x;
    int node = (int)(gid >> 5);
    if (node >= NN) return;
    int lane = threadIdx.x & 31;
    float4 hv = ((const float4*)(h + (size_t)node * 128))[lane];
    float4 w0 = ((const float4*)Wl2)[lane];
    float4 w1 = ((const float4*)(Wl2 + 128))[lane];
    float d0 = hv.x * w0.x + hv.y * w0.y + hv.z * w0.z + hv.w * w0.w;
    float d1 = hv.x * w1.x + hv.y * w1.y + hv.z * w1.z + hv.w * w1.w;
#pragma unroll
    for (int o = 16; o; o >>= 1) {
        d0 += __shfl_xor_sync(0xffffffffu, d0, o);
        d1 += __shfl_xor_sync(0xffffffffu, d1, o);
    }
    if (lane == 0) {
        g_z2[node * 2]     = d0;
        g_z2[node * 2 + 1] = d1;
    }
}

// Output: out[n] = mean_{s in N(n)} z2[s] + bl2 + h1[n] @ Wr2^T ; warp per node.
__global__ void out2_k(const float* __restrict__ h, const float* __restrict__ Wr2,
                       const float* __restrict__ bl2, float* __restrict__ out) {
    long long gid = (long long)blockIdx.x * blockDim.x + threadIdx.x;
    int node = (int)(gid >> 5);
    if (node >= NN) return;
    int lane = threadIdx.x & 31;

    float4 hv = ((const float4*)(h + (size_t)node * 128))[lane];
    float4 w0 = ((const float4*)Wr2)[lane];
    float4 w1 = ((const float4*)(Wr2 + 128))[lane];
    float d0 = hv.x * w0.x + hv.y * w0.y + hv.z * w0.z + hv.w * w0.w;
    float d1 = hv.x * w1.x + hv.y * w1.y + hv.z * w1.z + hv.w * w1.w;

    int beg = g_rowstart[node];
    int end = g_rowstart[node + 1];
    float a0 = 0.f, a1 = 0.f;
    for (int j = beg + lane; j < end; j += 32) {
        int s = g_csrc[j];
        float2 v = ((const float2*)g_z2)[s];
        a0 += v.x; a1 += v.y;
    }
#pragma unroll
    for (int o = 16; o; o >>= 1) {
        d0 += __shfl_xor_sync(0xffffffffu, d0, o);
        d1 += __shfl_xor_sync(0xffffffffu, d1, o);
        a0 += __shfl_xor_sync(0xffffffffu, a0, o);
        a1 += __shfl_xor_sync(0xffffffffu, a1, o);
    }
    if (lane == 0) {
        float iv = g_inv[node];
        out[node * 2]     = a0 * iv + bl2[0] + d0;
        out[node * 2 + 1] = a1 * iv + bl2[1] + d1;
    }
}

// ---------------------------------------------------------------------------
// Launch
// ---------------------------------------------------------------------------
extern "C" void kernel_launch(void* const* d_in, const int* in_sizes, int n_in,
                              void* d_out, int out_size)
{
    const float* x     = (const float*)d_in[0];
    const void*  ei    = d_in[1];                 // dtype runtime-detected
    const float* Wl0   = (const float*)d_in[2];
    const float* bl0   = (const float*)d_in[3];
    const float* Wr0   = (const float*)d_in[4];
    const float* Wl1   = (const float*)d_in[5];
    const float* bl1   = (const float*)d_in[6];
    const float* Wr1   = (const float*)d_in[7];
    const float* Wl2   = (const float*)d_in[8];
    const float* bl2   = (const float*)d_in[9];
    const float* Wr2   = (const float*)d_in[10];
    const float* Wres0 = (const float*)d_in[11];
    const float* bn0g  = (const float*)d_in[12];
    const float* bn0b  = (const float*)d_in[13];
    const float* bn0m  = (const float*)d_in[14];
    const float* bn0v  = (const float*)d_in[15];
    const float* bn1g  = (const float*)d_in[16];
    const float* bn1b  = (const float*)d_in[17];
    const float* bn1m  = (const float*)d_in[18];
    const float* bn1v  = (const float*)d_in[19];
    float* out = (float*)d_out;

    float *y, *r, *p, *h0, *h1;
    int* deg;
    cudaGetSymbolAddress((void**)&y,   g_y);
    cudaGetSymbolAddress((void**)&r,   g_r);
    cudaGetSymbolAddress((void**)&p,   g_p);
    cudaGetSymbolAddress((void**)&h0,  g_h0);
    cudaGetSymbolAddress((void**)&h1,  g_h1);
    cudaGetSymbolAddress((void**)&deg, g_deg);

    const int T = 256;
    const int gemm_bx = (NN + 127) / 128;                     // 391
    const int node_warp_blocks = (NN * 32 + T - 1) / T;       // 6250

    // ----- CSR build (graph is an input; rebuilt each launch) -----
    detect_k<<<1, 32>>>(ei);
    zero_i<<<(NN + T - 1) / T, T>>>(deg, NN);
    degree_k<<<(NE + T - 1) / T, T>>>(ei);
    bsum_k<<<NBLK, SCAN_B>>>();
    bscan_k<<<1, 256>>>();
    rowstart_k<<<NBLK, SCAN_B>>>();
    fill_k<<<(NE + T - 1) / T, T>>>(ei);

    // ----- layer 0: 3 GEMMs in one launch, then fused agg+BN+ReLU+res -----
    sgemm_n128_b<<<dim3(gemm_bx, 3), T>>>(x, Wl0, Wr0, Wres0, y, r, p, NN, KIN);
    agg_epi_k<<<node_warp_blocks, T>>>(y, r, p, bl0, bn0g, bn0b, bn0m, bn0v, h0);

    // ----- layer 1 -----
    sgemm_n128_b<<<dim3(gemm_bx, 2), T>>>(h0, Wl1, Wr1, Wr1, y, r, r, NN, HID);
    agg_epi_k<<<node_warp_blocks, T>>>(y, r, h0, bl1, bn1g, bn1b, bn1m, bn1v, h1);

    // ----- layer 2: transform to 2 dims first, then gather-side mean -----
    z2_k<<<node_warp_blocks, T>>>(h1, Wl2);
    out2_k<<<node_warp_blocks, T>>>(h1, Wr2, bl2, out);
}